// round 9
// baseline (speedup 1.0000x reference)
#include <cuda_runtime.h>
#include <cuda_fp16.h>
#include <cstdint>
#include <cstddef>

#define B_ 2048
#define T_ 200
#define D_ 4
#define H_ 256
#define G_ 1024
#define CL 8
#define THREADS 512
#define CH 16384
#define TILE 65536

// smem layout (bytes)
#define SW0_OFF   0                   // W0: 4 chunks * 16KB = 64KB
#define SW1_OFF   65536               // W1: 8 chunks * 16KB = 128KB
#define SLOT0     196608              // ring slot 0 (16KB)
#define SLOT1     (196608 + CH)       // ring slot 1 (16KB)
#define SXW_OFF   229376              // Wx fp16: 128*4 halves = 1KB
#define SXR_OFF   230400              // x rows fp16: 128*4 halves = 1KB
#define SMBAR_OFF 231424              // 2 mbarriers
#define SMEM_TOTAL 231488

// ---------------- device globals (pre-swizzled SMEM images) ----------------
__device__ __align__(128) __half g_W0[G_ * H_];        // 8 ranks * 64KB
__device__ __align__(128) __half g_Wx0h[G_ * D_];
__device__ __align__(128) float  g_b0[G_];
__device__ __align__(128) __half g_W1[G_ * 2 * H_];    // 8 ranks * 128KB
__device__ __align__(128) float  g_b1[G_];
__device__ __align__(128) __half g_zero[B_ * H_];
__device__ __align__(128) __half g_h1seq[(size_t)T_ * B_ * H_];  // [t*16+ms] tiles
__device__ __align__(128) __half g_h2a[B_ * H_];       // h2 at even t
__device__ __align__(128) __half g_h2b[B_ * H_];       // h2 at odd t
__device__ __align__(128) float  g_h2f[B_ * H_];

__global__ void k_init() {
    int s = gridDim.x * blockDim.x;
    for (int i = blockIdx.x * blockDim.x + threadIdx.x; i < B_ * H_; i += s)
        g_zero[i] = __float2half(0.f);
}
__device__ __forceinline__ size_t swoff(int r, int k) {
    int kc = k >> 6, cc = k & 63, g = cc >> 3, e = cc & 7;
    return (size_t)kc * CH + r * 128 + ((g ^ (r & 7)) << 4) + e * 2;
}
__global__ void k_pack0(const float* __restrict__ Wi, const float* __restrict__ Wh,
                        const float* __restrict__ bi, const float* __restrict__ bh) {
    int s = gridDim.x * blockDim.x;
    for (int i = blockIdx.x * blockDim.x + threadIdx.x; i < G_ * H_; i += s) {
        int n = i >> 8, k = i & 255;
        int j = n >> 2, g = n & 3, orow = g * H_ + j;
        int rank = n >> 7, r = n & 127;
        char* dst = (char*)g_W0 + (size_t)rank * TILE + swoff(r, k);
        *(__half*)dst = __float2half(Wh[orow * H_ + k]);
        if (k < D_) g_Wx0h[n * D_ + k] = __float2half(Wi[orow * D_ + k]);
        if (k == 0) g_b0[n] = bi[orow] + bh[orow];
    }
}
__global__ void k_pack1(const float* __restrict__ Wi, const float* __restrict__ Wh,
                        const float* __restrict__ bi, const float* __restrict__ bh) {
    int s = gridDim.x * blockDim.x;
    for (int i = blockIdx.x * blockDim.x + threadIdx.x; i < G_ * 512; i += s) {
        int n = i >> 9, k = i & 511;
        int j = n >> 2, g = n & 3, orow = g * H_ + j;
        int rank = n >> 7, r = n & 127;
        float v = (k < H_) ? Wi[orow * H_ + k] : Wh[orow * H_ + (k - H_)];
        char* dst = (char*)g_W1 + (size_t)rank * 131072 + swoff(r, k);
        *(__half*)dst = __float2half(v);
        if (k == 0) g_b1[n] = bi[orow] + bh[orow];
    }
}

// ---------------- helpers ----------------
__device__ __forceinline__ uint32_t smem_u32(const void* p) {
    uint32_t a;
    asm("{ .reg .u64 t; cvta.to.shared.u64 t, %1; cvt.u32.u64 %0, t; }" : "=r"(a) : "l"(p));
    return a;
}
__device__ __forceinline__ void clsync() {
    asm volatile("barrier.cluster.arrive.aligned;\n" ::: "memory");
    asm volatile("barrier.cluster.wait.aligned;\n" ::: "memory");
}
__device__ __forceinline__ float sig_(float x) {
    float e; asm("ex2.approx.ftz.f32 %0, %1;" : "=f"(e) : "f"(x * -1.44269504f));
    float r; asm("rcp.approx.ftz.f32 %0, %1;" : "=f"(r) : "f"(1.0f + e));
    return r;
}
__device__ __forceinline__ float tanh_(float x) { return __fmaf_rn(2.f, sig_(2.f * x), -1.f); }
__device__ __forceinline__ void mbar_init(uint32_t m, uint32_t c) {
    asm volatile("mbarrier.init.shared.b64 [%0], %1;" :: "r"(m), "r"(c) : "memory");
}
__device__ __forceinline__ void bulk_in(uint32_t sdst, const void* g, uint32_t bytes, uint32_t mb) {
    asm volatile("mbarrier.arrive.expect_tx.shared.b64 _, [%0], %1;" :: "r"(mb), "r"(bytes) : "memory");
    asm volatile("cp.async.bulk.shared::cluster.global.mbarrier::complete_tx::bytes [%0], [%1], %2, [%3];"
                 :: "r"(sdst), "l"(g), "r"(bytes), "r"(mb) : "memory");
}
__device__ __forceinline__ void mbar_wait(uint32_t m, uint32_t par) {
    uint32_t done;
    asm volatile(
        "{\n\t.reg .pred p;\n\t"
        "mbarrier.try_wait.parity.acquire.cta.shared::cta.b64 p, [%1], %2;\n\t"
        "selp.b32 %0, 1, 0, p;\n\t}"
        : "=r"(done) : "r"(m), "r"(par) : "memory");
    if (!done) {
        asm volatile(
            "{\n\t.reg .pred P1;\n\t"
            "WL_%=:\n\t"
            "mbarrier.try_wait.parity.acquire.cta.shared::cta.b64 P1, [%0], %1, 0x989680;\n\t"
            "@P1 bra.uni WD_%=;\n\t"
            "bra.uni WL_%=;\n\t"
            "WD_%=:\n\t}"
            :: "r"(m), "r"(par) : "memory");
    }
}
__device__ __forceinline__ void load4h(const __half* p, float f[4]) {
    uint2 u = *(const uint2*)p;
    __half2 h0 = *reinterpret_cast<__half2*>(&u.x);
    __half2 h1 = *reinterpret_cast<__half2*>(&u.y);
    float2 a = __half22float2(h0), b = __half22float2(h1);
    f[0] = a.x; f[1] = a.y; f[2] = b.x; f[3] = b.y;
}

// ---------------- GEMM on one resident chunk ----------------
__device__ __forceinline__ void gemm_chunk(
    const char* smem, int aoff, int boff, float (&acc)[2][4][4],
    int wm, int wn, int a_rowoff, int a_half, int b_rowoff, int b_half)
{
    const __half* sA = (const __half*)(smem + aoff);
    const __half* sB = (const __half*)(smem + boff);
#pragma unroll
    for (int k16 = 0; k16 < 4; k16++) {
        uint32_t afr[2][4];
#pragma unroll
        for (int mi = 0; mi < 2; mi++) {
            int r = wm * 32 + mi * 16 + a_rowoff;
            int cch = (k16 * 2 + a_half) ^ (r & 7);
            uint32_t ad = (uint32_t)__cvta_generic_to_shared(sA + r * 64 + cch * 8);
            asm volatile("ldmatrix.sync.aligned.m8n8.x4.shared.b16 {%0,%1,%2,%3}, [%4];\n"
                         : "=r"(afr[mi][0]), "=r"(afr[mi][1]), "=r"(afr[mi][2]), "=r"(afr[mi][3])
                         : "r"(ad));
        }
        uint32_t bfr[2][4];
#pragma unroll
        for (int np = 0; np < 2; np++) {
            int r = wn * 32 + np * 16 + b_rowoff;
            int cch = (k16 * 2 + b_half) ^ (r & 7);
            uint32_t ad = (uint32_t)__cvta_generic_to_shared(sB + r * 64 + cch * 8);
            asm volatile("ldmatrix.sync.aligned.m8n8.x4.shared.b16 {%0,%1,%2,%3}, [%4];\n"
                         : "=r"(bfr[np][0]), "=r"(bfr[np][1]), "=r"(bfr[np][2]), "=r"(bfr[np][3])
                         : "r"(ad));
        }
#pragma unroll
        for (int mi = 0; mi < 2; mi++)
#pragma unroll
            for (int nj = 0; nj < 4; nj++) {
                uint32_t b0 = bfr[nj >> 1][(nj & 1) * 2 + 0];
                uint32_t b1 = bfr[nj >> 1][(nj & 1) * 2 + 1];
                asm volatile(
                    "mma.sync.aligned.m16n8k16.row.col.f32.f16.f16.f32 "
                    "{%0,%1,%2,%3}, {%4,%5,%6,%7}, {%8,%9}, {%0,%1,%2,%3};\n"
                    : "+f"(acc[mi][nj][0]), "+f"(acc[mi][nj][1]),
                      "+f"(acc[mi][nj][2]), "+f"(acc[mi][nj][3])
                    : "r"(afr[mi][0]), "r"(afr[mi][1]), "r"(afr[mi][2]), "r"(afr[mi][3]),
                      "r"(b0), "r"(b1));
            }
    }
}

// ---------------- pointwise (gates -> c,h), stage into smem ----------------
template<bool XPROJ, bool FIN>
__device__ __forceinline__ void pointwise(
    float (&acc)[2][4][4], float* cst, const float* biasr,
    char* smem, int stage_off, int lane, int wm, int wn)
{
    const int q = lane & 3;
    const bool oddq = (q & 1) != 0;
    const __half* sxr = (const __half*)(smem + SXR_OFF);
    const __half* sxw = (const __half*)(smem + SXW_OFF);
    __half* hs = (__half*)(smem + stage_off);
    float*  fs = (float*)(smem + stage_off);

#pragma unroll
    for (int mi = 0; mi < 2; mi++) {
        int r0 = wm * 32 + mi * 16 + (lane >> 2);
        float xlo[4], xhi[4];
        if (XPROJ) {
            load4h(sxr + r0 * 4, xlo);
            load4h(sxr + (r0 + 8) * 4, xhi);
        }
#pragma unroll
        for (int nj = 0; nj < 4; nj++) {
            float a0 = acc[mi][nj][0] + biasr[nj * 2 + 0];
            float a1 = acc[mi][nj][1] + biasr[nj * 2 + 1];
            float a2 = acc[mi][nj][2] + biasr[nj * 2 + 0];
            float a3 = acc[mi][nj][3] + biasr[nj * 2 + 1];
            if (XPROJ) {
                int cl = wn * 32 + nj * 8 + q * 2;
                float w0[4], w1[4];
                load4h(sxw + cl * 4, w0);
                load4h(sxw + cl * 4 + 4, w1);
                a0 += xlo[0]*w0[0] + xlo[1]*w0[1] + xlo[2]*w0[2] + xlo[3]*w0[3];
                a1 += xlo[0]*w1[0] + xlo[1]*w1[1] + xlo[2]*w1[2] + xlo[3]*w1[3];
                a2 += xhi[0]*w0[0] + xhi[1]*w0[1] + xhi[2]*w0[2] + xhi[3]*w0[3];
                a3 += xhi[0]*w1[0] + xhi[1]*w1[1] + xhi[2]*w1[2] + xhi[3]*w1[3];
            }
            float e0 = __shfl_xor_sync(0xffffffffu, a0, 1);
            float e1 = __shfl_xor_sync(0xffffffffu, a1, 1);
            float e2 = __shfl_xor_sync(0xffffffffu, a2, 1);
            float e3 = __shfl_xor_sync(0xffffffffu, a3, 1);
            float gi, gf, gg, go; int row;
            if (!oddq) { gi = a0; gf = a1; gg = e0; go = e1; row = r0; }
            else       { gi = e2; gf = e3; gg = a2; go = a3; row = r0 + 8; }
            int ci = mi * 4 + nj;
            float iv = sig_(gi), fv = sig_(gf), gv = tanh_(gg), ov = sig_(go);
            float cn = fv * cst[ci] + iv * gv;
            cst[ci] = cn;
            float h = ov * tanh_(cn);
            int jl = wn * 8 + nj * 2 + (q >> 1);
            if (FIN) fs[row * 32 + jl] = h;
            else     hs[row * 32 + jl] = __float2half(h);
        }
    }
}

// ---------------- one fused round ----------------
// L0 at t=r (if DO0): gates0 = h1(r-1) @ W0 (+x proj) -> h1(r)
// L1 at t=r-1 (if DO1): gates1 = [h2(r-2) | h1(r-1)] @ W1 -> h2(r-1)
template<bool DO0, bool DO1, bool FIN>
__device__ __forceinline__ void round(
    const char* __restrict__ h1p, const char* __restrict__ h2p,
    char* __restrict__ h1d, char* __restrict__ h2d,
    float* __restrict__ fdst, const float* __restrict__ xg,
    float* c0st, float* c1st, const float* b0r, const float* b1r, int* uc,
    char* smem, uint32_t sb32, int tid, int lane, int wm, int wn, int rank,
    int a_rowoff, int a_half, int b_rowoff, int b_half)
{
    const uint32_t mb0 = sb32 + SMBAR_OFF, mb1 = sb32 + SMBAR_OFF + 8;
    float acc[2][4][4];

    if (DO0 && tid < 128) {
        float4 v = *(const float4*)(xg + (size_t)tid * (T_ * D_));
        __half2 p0 = __floats2half2_rn(v.x, v.y);
        __half2 p1 = __floats2half2_rn(v.z, v.w);
        uint2 u;
        u.x = *reinterpret_cast<uint32_t*>(&p0);
        u.y = *reinterpret_cast<uint32_t*>(&p1);
        *(uint2*)((__half*)(smem + SXR_OFF) + tid * 4) = u;
    }
    if (tid == 0) {
        if (DO0) {
            bulk_in(sb32 + SLOT0, h1p + 0 * CH, CH, mb0);
            bulk_in(sb32 + SLOT1, h1p + 1 * CH, CH, mb1);
        } else {
            bulk_in(sb32 + SLOT0, h2p + 0 * CH, CH, mb0);
            bulk_in(sb32 + SLOT1, h2p + 1 * CH, CH, mb1);
        }
    }

    if (DO0) {
#pragma unroll
        for (int mi = 0; mi < 2; mi++)
#pragma unroll
            for (int nj = 0; nj < 4; nj++)
#pragma unroll
                for (int e = 0; e < 4; e++) acc[mi][nj][e] = 0.f;
        // chunk 0 (s0)
        mbar_wait(mb0, uc[0] & 1); uc[0]++;
        gemm_chunk(smem, SLOT0, SW0_OFF + 0 * CH, acc, wm, wn, a_rowoff, a_half, b_rowoff, b_half);
        __syncthreads();
        if (tid == 0) bulk_in(sb32 + SLOT0, h1p + 2 * CH, CH, mb0);
        // chunk 1 (s1)
        mbar_wait(mb1, uc[1] & 1); uc[1]++;
        gemm_chunk(smem, SLOT1, SW0_OFF + 1 * CH, acc, wm, wn, a_rowoff, a_half, b_rowoff, b_half);
        __syncthreads();
        if (tid == 0) bulk_in(sb32 + SLOT1, h1p + 3 * CH, CH, mb1);
        // chunk 2 (s0)
        mbar_wait(mb0, uc[0] & 1); uc[0]++;
        gemm_chunk(smem, SLOT0, SW0_OFF + 2 * CH, acc, wm, wn, a_rowoff, a_half, b_rowoff, b_half);
        __syncthreads();
        if (DO1 && tid == 0) bulk_in(sb32 + SLOT0, h2p + 0 * CH, CH, mb0);
        // chunk 3 (s1)
        mbar_wait(mb1, uc[1] & 1); uc[1]++;
        gemm_chunk(smem, SLOT1, SW0_OFF + 3 * CH, acc, wm, wn, a_rowoff, a_half, b_rowoff, b_half);
        __syncthreads();
        // pointwise L0: stage h1(r) into SLOT1 (free), flush to global
        pointwise<true, false>(acc, c0st, b0r, smem, SLOT1, lane, wm, wn);
        __syncthreads();
        {
            int row = tid >> 2, gg2 = tid & 3;
            uint4 v = *(uint4*)(smem + SLOT1 + row * 64 + gg2 * 16);
            int kcc = rank >> 1;
            int g2 = ((rank & 1) << 2) | gg2;
            *(uint4*)(h1d + kcc * CH + row * 128 + ((g2 ^ (row & 7)) << 4)) = v;
        }
        __syncthreads();
        if (DO1 && tid == 0) bulk_in(sb32 + SLOT1, h2p + 1 * CH, CH, mb1);
    }

    if (DO1) {
#pragma unroll
        for (int mi = 0; mi < 2; mi++)
#pragma unroll
            for (int nj = 0; nj < 4; nj++)
#pragma unroll
                for (int e = 0; e < 4; e++) acc[mi][nj][e] = 0.f;
#pragma unroll 1
        for (int j = 0; j < 8; j++) {
            const int s = j & 1;
            mbar_wait(sb32 + SMBAR_OFF + s * 8, uc[s] & 1); uc[s]++;
            int wj = (j < 4) ? (4 + j) : (j - 4);
            gemm_chunk(smem, (s ? SLOT1 : SLOT0), SW1_OFF + wj * CH, acc,
                       wm, wn, a_rowoff, a_half, b_rowoff, b_half);
            __syncthreads();
            if (tid == 0 && j + 2 < 8) {
                int p = j + 2;
                const char* src = (p < 4) ? (h2p + p * CH) : (h1p + (p - 4) * CH);
                bulk_in(sb32 + (s ? SLOT1 : SLOT0), src, CH, sb32 + SMBAR_OFF + s * 8);
            }
        }
        // pointwise L1: stage into SLOT0
        pointwise<false, FIN>(acc, c1st, b1r, smem, SLOT0, lane, wm, wn);
        __syncthreads();
        if (FIN) {
#pragma unroll
            for (int p = 0; p < 8; p++) {
                int row = p * 16 + (tid >> 5);
                int cc = tid & 31;
                fdst[(size_t)row * H_ + cc] = *(float*)(smem + SLOT0 + (row * 32 + cc) * 4);
            }
        } else {
            int row = tid >> 2, gg2 = tid & 3;
            uint4 v = *(uint4*)(smem + SLOT0 + row * 64 + gg2 * 16);
            int kcc = rank >> 1;
            int g2 = ((rank & 1) << 2) | gg2;
            *(uint4*)(h2d + kcc * CH + row * 128 + ((g2 ^ (row & 7)) << 4)) = v;
        }
    }

    asm volatile("fence.proxy.async;" ::: "memory");
    clsync();
}

// ---------------- persistent kernel ----------------
__global__ void __cluster_dims__(CL, 1, 1) __launch_bounds__(THREADS, 1)
k_lstm(const float* __restrict__ x)
{
    extern __shared__ __align__(1024) char smem[];
    uint32_t sb32 = smem_u32(smem);
    const int tid  = threadIdx.x;
    const int lane = tid & 31;
    const int warp = tid >> 5;
    const int wm = warp & 3;
    const int wn = warp >> 2;
    const int rank = blockIdx.x;
    const int ms   = blockIdx.y;
    const int mbase = ms * 128;
    const int nbase = rank * 128;
    const int q = lane & 3;

    const int lg = lane >> 3, lr = lane & 7;
    const int a_rowoff = lr + ((lg & 1) << 3);
    const int a_half   = lg >> 1;
    const int b_rowoff = lr + ((lg >> 1) << 3);
    const int b_half   = lg & 1;

    const uint32_t mb0 = sb32 + SMBAR_OFF, mb1 = sb32 + SMBAR_OFF + 8;
    if (tid == 0) { mbar_init(mb0, 1); mbar_init(mb1, 1); }
    __syncthreads();

    int uc[2] = {0, 0};
    float c0st[8], c1st[8], b0r[8], b1r[8];

    // load weights once (via slot barriers), Wx fp16, biases to regs
    if (tid == 0) {
        bulk_in(sb32 + SW0_OFF, (char*)g_W0 + (size_t)rank * TILE, TILE, mb0);
        bulk_in(sb32 + SW1_OFF, (char*)g_W1 + (size_t)rank * 131072, 131072, mb1);
    }
    if (tid < 128) {
        *(uint2*)((__half*)(smem + SXW_OFF) + tid * 4) =
            *(const uint2*)&g_Wx0h[(nbase + tid) * 4];
    }
#pragma unroll
    for (int nj = 0; nj < 4; nj++) {
        b0r[nj * 2 + 0] = g_b0[nbase + wn * 32 + nj * 8 + q * 2 + 0];
        b0r[nj * 2 + 1] = g_b0[nbase + wn * 32 + nj * 8 + q * 2 + 1];
        b1r[nj * 2 + 0] = g_b1[nbase + wn * 32 + nj * 8 + q * 2 + 0];
        b1r[nj * 2 + 1] = g_b1[nbase + wn * 32 + nj * 8 + q * 2 + 1];
    }
#pragma unroll
    for (int i = 0; i < 8; i++) { c0st[i] = 0.f; c1st[i] = 0.f; }
    mbar_wait(mb0, uc[0] & 1); uc[0]++;
    mbar_wait(mb1, uc[1] & 1); uc[1]++;
    __syncthreads();

    const char* zt = (const char*)g_zero + (size_t)ms * TILE;
    char* h2at = (char*)g_h2a + (size_t)ms * TILE;
    char* h2bt = (char*)g_h2b + (size_t)ms * TILE;
    auto h1tile = [&](int t) -> char* {
        return (char*)g_h1seq + ((size_t)t * 16 + ms) * TILE;
    };

    // round 0: L0 only (t=0), h1prev = zero
    round<true, false, false>(zt, nullptr, h1tile(0), nullptr, nullptr,
                              x + ((size_t)mbase * T_ + 0) * D_,
                              c0st, c1st, b0r, b1r, uc,
                              smem, sb32, tid, lane, wm, wn, rank,
                              a_rowoff, a_half, b_rowoff, b_half);

    // rounds 1..199: L0 t=r, L1 t=r-1
#pragma unroll 1
    for (int r = 1; r < T_; r++) {
        const char* h1p = h1tile(r - 1);
        const char* h2p = (r == 1) ? zt : ((r & 1) ? h2bt : h2at);   // h2(r-2)
        char* h2d = ((r - 1) & 1) ? h2bt : h2at;                     // h2(r-1)
        round<true, true, false>(h1p, h2p, h1tile(r), h2d, nullptr,
                                 x + ((size_t)mbase * T_ + r) * D_,
                                 c0st, c1st, b0r, b1r, uc,
                                 smem, sb32, tid, lane, wm, wn, rank,
                                 a_rowoff, a_half, b_rowoff, b_half);
    }

    // round 200: L1 only (t=199), h2prev = h2(198) = even -> a
    round<false, true, true>(h1tile(T_ - 1), h2at, nullptr, nullptr,
                             g_h2f + (size_t)mbase * H_ + rank * 32, nullptr,
                             c0st, c1st, b0r, b1r, uc,
                             smem, sb32, tid, lane, wm, wn, rank,
                             a_rowoff, a_half, b_rowoff, b_half);
}

// ---------------- final FC ----------------
__global__ void k_fc(const float* __restrict__ Wfc, const float* __restrict__ bfc,
                     float* __restrict__ out) {
    int b = blockIdx.x;
    int o = threadIdx.y;
    int lane = threadIdx.x;
    const float* hr = g_h2f + (size_t)b * H_;
    const float* wr = Wfc + (size_t)o * H_;
    float s = 0.f;
    for (int j = lane; j < H_; j += 32) s += hr[j] * wr[j];
#pragma unroll
    for (int off = 16; off; off >>= 1) s += __shfl_xor_sync(0xffffffffu, s, off);
    if (lane == 0) out[b * 6 + o] = s + bfc[o];
}

// ---------------- host ----------------
extern "C" void kernel_launch(void* const* d_in, const int* in_sizes, int n_in,
                              void* d_out, int out_size) {
    const float* x     = (const float*)d_in[0];
    const float* W_ih0 = (const float*)d_in[1];
    const float* W_hh0 = (const float*)d_in[2];
    const float* b_ih0 = (const float*)d_in[3];
    const float* b_hh0 = (const float*)d_in[4];
    const float* W_ih1 = (const float*)d_in[5];
    const float* W_hh1 = (const float*)d_in[6];
    const float* b_ih1 = (const float*)d_in[7];
    const float* b_hh1 = (const float*)d_in[8];
    const float* W_fc  = (const float*)d_in[9];
    const float* b_fc  = (const float*)d_in[10];

    cudaFuncSetAttribute(k_lstm, cudaFuncAttributeMaxDynamicSharedMemorySize, SMEM_TOTAL);

    k_init<<<256, 256>>>();
    k_pack0<<<512, 256>>>(W_ih0, W_hh0, b_ih0, b_hh0);
    k_pack1<<<1024, 256>>>(W_ih1, W_hh1, b_ih1, b_hh1);

    k_lstm<<<dim3(CL, 16), THREADS, SMEM_TOTAL>>>(x);

    k_fc<<<B_, dim3(32, 6)>>>(W_fc, b_fc, (float*)d_out);
}

// round 10
// speedup vs baseline: 1.2613x; 1.2613x over previous
#include <cuda_runtime.h>
#include <cuda_fp16.h>
#include <cstdint>
#include <cstddef>

#define B_ 2048
#define T_ 200
#define D_ 4
#define H_ 256
#define G_ 1024
#define CL 8
#define THREADS 512
#define CH 16384
#define TILE 65536

// smem layout (bytes)
#define SW_OFF    0                       // W: up to 8 chunks * 16KB = 128KB
#define SXW_OFF   65536                   // phase A only (upper half of W region): Wx fp16
#define SXR_OFF   (SXW_OFF + 2048)        // phase A only: x rows fp16
#define RING_OFF  131072                  // 6 slots * 16KB = 96KB
#define HSTG_OFF  (RING_OFF + 4*CH)       // h staging = ring slot 4 (16KB)
#define SMBAR_OFF (RING_OFF + 6*CH)       // 7 mbarriers
#define SMEM_TOTAL (SMBAR_OFF + 64)

// ---------------- device globals (pre-swizzled SMEM images) ----------------
__device__ __align__(128) __half g_W0[G_ * H_];        // 8 ranks * 64KB
__device__ __align__(128) __half g_Wx0h[G_ * D_];
__device__ __align__(128) float  g_b0[G_];
__device__ __align__(128) __half g_W1[G_ * 2 * H_];    // 8 ranks * 128KB
__device__ __align__(128) float  g_b1[G_];
__device__ __align__(128) __half g_zero[B_ * H_];
__device__ __align__(128) __half g_h1seq[(size_t)T_ * B_ * H_];  // [t*16+ms] tiles
__device__ __align__(128) __half g_h2a[B_ * H_];
__device__ __align__(128) __half g_h2b[B_ * H_];
__device__ __align__(128) float  g_h2f[B_ * H_];

__global__ void k_init() {
    int s = gridDim.x * blockDim.x;
    for (int i = blockIdx.x * blockDim.x + threadIdx.x; i < B_ * H_; i += s)
        g_zero[i] = __float2half(0.f);
}
__device__ __forceinline__ size_t swoff(int r, int k) {
    int kc = k >> 6, cc = k & 63, g = cc >> 3, e = cc & 7;
    return (size_t)kc * CH + r * 128 + ((g ^ (r & 7)) << 4) + e * 2;
}
// quad-in-thread column map: within each 32-col group
//   [i0 f0 i1 f1 i2 f2 i3 f3 | g0 o0 g1 o1 g2 o2 g3 o3 | i4 f4.. | g4 o4..]
__device__ __forceinline__ int col2row(int n) {
    int c = n & 31;
    int j = (n >> 5) * 8 + ((c >> 4) << 2) + ((c >> 1) & 3);
    int blk = (c >> 3) & 1, e = c & 1;
    int g = blk ? (e ? 3 : 2) : (e ? 1 : 0);
    return g * H_ + j;
}
__global__ void k_pack0(const float* __restrict__ Wi, const float* __restrict__ Wh,
                        const float* __restrict__ bi, const float* __restrict__ bh) {
    int s = gridDim.x * blockDim.x;
    for (int i = blockIdx.x * blockDim.x + threadIdx.x; i < G_ * H_; i += s) {
        int n = i >> 8, k = i & 255;
        int orow = col2row(n);
        int rank = n >> 7, r = n & 127;
        char* dst = (char*)g_W0 + (size_t)rank * TILE + swoff(r, k);
        *(__half*)dst = __float2half(Wh[orow * H_ + k]);
        if (k < D_) g_Wx0h[n * D_ + k] = __float2half(Wi[orow * D_ + k]);
        if (k == 0) g_b0[n] = bi[orow] + bh[orow];
    }
}
__global__ void k_pack1(const float* __restrict__ Wi, const float* __restrict__ Wh,
                        const float* __restrict__ bi, const float* __restrict__ bh) {
    int s = gridDim.x * blockDim.x;
    for (int i = blockIdx.x * blockDim.x + threadIdx.x; i < G_ * 512; i += s) {
        int n = i >> 9, k = i & 511;
        int orow = col2row(n);
        int rank = n >> 7, r = n & 127;
        float v = (k < H_) ? Wi[orow * H_ + k] : Wh[orow * H_ + (k - H_)];
        char* dst = (char*)g_W1 + (size_t)rank * 131072 + swoff(r, k);
        *(__half*)dst = __float2half(v);
        if (k == 0) g_b1[n] = bi[orow] + bh[orow];
    }
}

// ---------------- helpers ----------------
__device__ __forceinline__ uint32_t smem_u32(const void* p) {
    uint32_t a;
    asm("{ .reg .u64 t; cvta.to.shared.u64 t, %1; cvt.u32.u64 %0, t; }" : "=r"(a) : "l"(p));
    return a;
}
__device__ __forceinline__ void clsync() {
    asm volatile("barrier.cluster.arrive.aligned;\n" ::: "memory");
    asm volatile("barrier.cluster.wait.aligned;\n" ::: "memory");
}
__device__ __forceinline__ float tanha_(float x) {
    float r; asm("tanh.approx.f32 %0, %1;" : "=f"(r) : "f"(x));
    return r;
}
__device__ __forceinline__ float siga_(float x) {
    return __fmaf_rn(tanha_(0.5f * x), 0.5f, 0.5f);
}
__device__ __forceinline__ void mbar_init(uint32_t m, uint32_t c) {
    asm volatile("mbarrier.init.shared.b64 [%0], %1;" :: "r"(m), "r"(c) : "memory");
}
__device__ __forceinline__ void bulk_in(uint32_t sdst, const void* g, uint32_t bytes, uint32_t mb) {
    asm volatile("mbarrier.arrive.expect_tx.shared.b64 _, [%0], %1;" :: "r"(mb), "r"(bytes) : "memory");
    asm volatile("cp.async.bulk.shared::cluster.global.mbarrier::complete_tx::bytes [%0], [%1], %2, [%3];"
                 :: "r"(sdst), "l"(g), "r"(bytes), "r"(mb) : "memory");
}
__device__ __forceinline__ void mbar_wait(uint32_t m, uint32_t par) {
    uint32_t done;
    asm volatile(
        "{\n\t.reg .pred p;\n\t"
        "mbarrier.try_wait.parity.acquire.cta.shared::cta.b64 p, [%1], %2;\n\t"
        "selp.b32 %0, 1, 0, p;\n\t}"
        : "=r"(done) : "r"(m), "r"(par) : "memory");
    if (!done) {
        asm volatile(
            "{\n\t.reg .pred P1;\n\t"
            "WL_%=:\n\t"
            "mbarrier.try_wait.parity.acquire.cta.shared::cta.b64 P1, [%0], %1, 0x989680;\n\t"
            "@P1 bra.uni WD_%=;\n\t"
            "bra.uni WL_%=;\n\t"
            "WD_%=:\n\t}"
            :: "r"(m), "r"(par) : "memory");
    }
}
__device__ __forceinline__ void load4h(const __half* p, float f[4]) {
    uint2 u = *(const uint2*)p;
    __half2 h0 = *reinterpret_cast<__half2*>(&u.x);
    __half2 h1 = *reinterpret_cast<__half2*>(&u.y);
    float2 a = __half22float2(h0), b = __half22float2(h1);
    f[0] = a.x; f[1] = a.y; f[2] = b.x; f[3] = b.y;
}

// ---------------- one LSTM step ----------------
// Phase A (PHB=false): 4 h chunks, x via pointwise. Phase B (PHB=true): 8 chunks,
// x chunks 0-3 prefetched into ring slots 0-3 by the PREVIOUS step; h chunks 4-7.
template<bool PHB>
__device__ __forceinline__ void run_step(
    const char* __restrict__ hsrc,        // h tile (4 chunks)
    const char* __restrict__ nx,          // PHB: next-step x tile to prefetch (or null)
    const float* __restrict__ xrow_g,     // phase A: x + (mbase*T + t)*D
    char* __restrict__ hdst_tile, float* __restrict__ fdst,
    float* c, const float* biasr, int* uc,
    char* smem, uint32_t sb32, int tid, int lane, int wm, int wn, int rank,
    int a_rowoff, int a_half, int b_rowoff, int b_half)
{
    if (!PHB && tid < 128) {
        float4 v = *(const float4*)(xrow_g + (size_t)tid * (T_ * D_));
        __half2 p0 = __floats2half2_rn(v.x, v.y);
        __half2 p1 = __floats2half2_rn(v.z, v.w);
        uint2 u;
        u.x = *reinterpret_cast<uint32_t*>(&p0);
        u.y = *reinterpret_cast<uint32_t*>(&p1);
        *(uint2*)((__half*)(smem + SXR_OFF) + tid * 4) = u;
    }

    if (tid == 0) {
        if (PHB) {
            bulk_in(sb32 + RING_OFF + 4 * CH, hsrc + 0 * CH, CH, sb32 + SMBAR_OFF + 4 * 8);
            bulk_in(sb32 + RING_OFF + 5 * CH, hsrc + 1 * CH, CH, sb32 + SMBAR_OFF + 5 * 8);
        } else {
#pragma unroll
            for (int p = 0; p < 4; p++)
                bulk_in(sb32 + RING_OFF + p * CH, hsrc + p * CH, CH, sb32 + SMBAR_OFF + p * 8);
        }
    }

    float acc[2][4][4];
#pragma unroll
    for (int mi = 0; mi < 2; mi++)
#pragma unroll
        for (int nj = 0; nj < 4; nj++)
#pragma unroll
            for (int e = 0; e < 4; e++) acc[mi][nj][e] = 0.f;

    const int NC = PHB ? 8 : 4;
#pragma unroll
    for (int kc = 0; kc < NC; kc++) {
        const int s = (kc < 6) ? kc : kc - 6;
        mbar_wait(sb32 + SMBAR_OFF + s * 8, uc[s] & 1);
        uc[s]++;
        const __half* sA = (const __half*)(smem + RING_OFF + s * CH);
        const __half* sB = (const __half*)(smem + SW_OFF + kc * CH);
#pragma unroll
        for (int k16 = 0; k16 < 4; k16++) {
            uint32_t afr[2][4];
#pragma unroll
            for (int mi = 0; mi < 2; mi++) {
                int r = wm * 32 + mi * 16 + a_rowoff;
                int cch = (k16 * 2 + a_half) ^ (r & 7);
                uint32_t ad = (uint32_t)__cvta_generic_to_shared(sA + r * 64 + cch * 8);
                asm volatile("ldmatrix.sync.aligned.m8n8.x4.shared.b16 {%0,%1,%2,%3}, [%4];\n"
                             : "=r"(afr[mi][0]), "=r"(afr[mi][1]), "=r"(afr[mi][2]), "=r"(afr[mi][3])
                             : "r"(ad));
            }
            uint32_t bfr[2][4];
#pragma unroll
            for (int np = 0; np < 2; np++) {
                int r = wn * 32 + np * 16 + b_rowoff;
                int cch = (k16 * 2 + b_half) ^ (r & 7);
                uint32_t ad = (uint32_t)__cvta_generic_to_shared(sB + r * 64 + cch * 8);
                asm volatile("ldmatrix.sync.aligned.m8n8.x4.shared.b16 {%0,%1,%2,%3}, [%4];\n"
                             : "=r"(bfr[np][0]), "=r"(bfr[np][1]), "=r"(bfr[np][2]), "=r"(bfr[np][3])
                             : "r"(ad));
            }
#pragma unroll
            for (int mi = 0; mi < 2; mi++)
#pragma unroll
                for (int nj = 0; nj < 4; nj++) {
                    uint32_t b0 = bfr[nj >> 1][(nj & 1) * 2 + 0];
                    uint32_t b1 = bfr[nj >> 1][(nj & 1) * 2 + 1];
                    asm volatile(
                        "mma.sync.aligned.m16n8k16.row.col.f32.f16.f16.f32 "
                        "{%0,%1,%2,%3}, {%4,%5,%6,%7}, {%8,%9}, {%0,%1,%2,%3};\n"
                        : "+f"(acc[mi][nj][0]), "+f"(acc[mi][nj][1]),
                          "+f"(acc[mi][nj][2]), "+f"(acc[mi][nj][3])
                        : "r"(afr[mi][0]), "r"(afr[mi][1]), "r"(afr[mi][2]), "r"(afr[mi][3]),
                          "r"(b0), "r"(b1));
                }
        }
        if (PHB && kc <= 1) {
            __syncthreads();
            if (tid == 0)
                bulk_in(sb32 + RING_OFF + kc * CH, hsrc + (2 + kc) * CH, CH,
                        sb32 + SMBAR_OFF + kc * 8);
        }
    }
    __syncthreads();   // all chunk reads complete; safe to prefetch + write hstg (slot 4)
    if (PHB && tid == 0 && nx) {
#pragma unroll
        for (int p = 0; p < 4; p++)
            bulk_in(sb32 + RING_OFF + p * CH, nx + p * CH, CH, sb32 + SMBAR_OFF + p * 8);
    }

    // ---------- pointwise (quad-in-thread, no shfl) ----------
    const int q = lane & 3;
    const bool fin = (fdst != nullptr);
    const __half* sxr = (const __half*)(smem + SXR_OFF);
    const __half* sxw = (const __half*)(smem + SXW_OFF);
    __half* hs = (__half*)(smem + HSTG_OFF);
    float*  fs = (float*)(smem + HSTG_OFF);

#pragma unroll
    for (int mi = 0; mi < 2; mi++) {
        int r0 = wm * 32 + mi * 16 + (lane >> 2);
        float a[4][4];
        float xlo[4], xhi[4];
        if (!PHB) {
            load4h(sxr + r0 * 4, xlo);
            load4h(sxr + (r0 + 8) * 4, xhi);
        }
#pragma unroll
        for (int nj = 0; nj < 4; nj++) {
            a[nj][0] = acc[mi][nj][0] + biasr[nj * 2 + 0];
            a[nj][1] = acc[mi][nj][1] + biasr[nj * 2 + 1];
            a[nj][2] = acc[mi][nj][2] + biasr[nj * 2 + 0];
            a[nj][3] = acc[mi][nj][3] + biasr[nj * 2 + 1];
            if (!PHB) {
                int cl = wn * 32 + nj * 8 + q * 2;
                float w0[4], w1[4];
                load4h(sxw + cl * 4, w0);
                load4h(sxw + cl * 4 + 4, w1);
                a[nj][0] += xlo[0]*w0[0] + xlo[1]*w0[1] + xlo[2]*w0[2] + xlo[3]*w0[3];
                a[nj][1] += xlo[0]*w1[0] + xlo[1]*w1[1] + xlo[2]*w1[2] + xlo[3]*w1[3];
                a[nj][2] += xhi[0]*w0[0] + xhi[1]*w0[1] + xhi[2]*w0[2] + xhi[3]*w0[3];
                a[nj][3] += xhi[0]*w1[0] + xhi[1]*w1[1] + xhi[2]*w1[2] + xhi[3]*w1[3];
            }
        }
#pragma unroll
        for (int us = 0; us < 2; us++)
#pragma unroll
            for (int ru = 0; ru < 2; ru++) {
                float gi = a[us * 2 + 0][ru * 2 + 0];
                float gf = a[us * 2 + 0][ru * 2 + 1];
                float gg = a[us * 2 + 1][ru * 2 + 0];
                float go = a[us * 2 + 1][ru * 2 + 1];
                int ci = mi * 4 + us * 2 + ru;
                float iv = siga_(gi), fv = siga_(gf), gv = tanha_(gg), ov = siga_(go);
                float cn = fv * c[ci] + iv * gv;
                c[ci] = cn;
                float h = ov * tanha_(cn);
                int row = r0 + ru * 8;
                int jl = wn * 8 + q + us * 4;
                if (fin) fs[row * 32 + jl] = h;
                else     hs[row * 32 + jl] = __float2half(h);
            }
    }
    __syncthreads();

    if (!fin) {
        int row = tid >> 2, gg2 = tid & 3;
        uint4 v = *(uint4*)&hs[row * 32 + gg2 * 8];
        int kcc = rank >> 1;
        int g2 = ((rank & 1) << 2) | gg2;
        *(uint4*)(hdst_tile + kcc * CH + row * 128 + ((g2 ^ (row & 7)) << 4)) = v;
    } else {
#pragma unroll
        for (int p = 0; p < 8; p++) {
            int row = p * 16 + (tid >> 5);
            int cc = tid & 31;
            fdst[(size_t)row * H_ + cc] = fs[row * 32 + cc];
        }
    }
    asm volatile("fence.proxy.async;" ::: "memory");
    clsync();
}

// ---------------- persistent kernel ----------------
__global__ void __cluster_dims__(CL, 1, 1) __launch_bounds__(THREADS, 1)
k_lstm(const float* __restrict__ x)
{
    extern __shared__ __align__(1024) char smem[];
    uint32_t sb32 = smem_u32(smem);
    const int tid  = threadIdx.x;
    const int lane = tid & 31;
    const int warp = tid >> 5;
    const int wm = warp & 3;
    const int wn = warp >> 2;
    const int rank = blockIdx.x;
    const int ms   = blockIdx.y;
    const int mbase = ms * 128;
    const int nbase = rank * 128;
    const int q = lane & 3;

    const int lg = lane >> 3, lr = lane & 7;
    const int a_rowoff = lr + ((lg & 1) << 3);
    const int a_half   = lg >> 1;
    const int b_rowoff = lr + ((lg >> 1) << 3);
    const int b_half   = lg & 1;

    if (tid == 0) {
#pragma unroll
        for (int s = 0; s < 7; s++) mbar_init(sb32 + SMBAR_OFF + s * 8, 1);
    }
    __syncthreads();

    __half* sxw = (__half*)(smem + SXW_OFF);
    float biasr[8], c[8];
    int uc[6] = {0, 0, 0, 0, 0, 0};
    const uint32_t mbW = sb32 + SMBAR_OFF + 48;

    // ---- phase A: layer 0 (K=256, x via pointwise) ----
    if (tid == 0) bulk_in(sb32 + SW_OFF, (char*)g_W0 + (size_t)rank * TILE, TILE, mbW);
    if (tid < 128)
        *(uint2*)(sxw + tid * 4) = *(const uint2*)&g_Wx0h[(nbase + tid) * 4];
#pragma unroll
    for (int nj = 0; nj < 4; nj++) {
        biasr[nj * 2 + 0] = g_b0[nbase + wn * 32 + nj * 8 + q * 2 + 0];
        biasr[nj * 2 + 1] = g_b0[nbase + wn * 32 + nj * 8 + q * 2 + 1];
    }
#pragma unroll
    for (int i = 0; i < 8; i++) c[i] = 0.f;
    mbar_wait(mbW, 0);
    __syncthreads();

    const char* zt = (const char*)g_zero + (size_t)ms * TILE;
#pragma unroll 1
    for (int t = 0; t < T_; t++) {
        const char* s1 = (t == 0) ? zt : ((const char*)g_h1seq + ((size_t)(t - 1) * 16 + ms) * TILE);
        char* hd = (char*)g_h1seq + ((size_t)t * 16 + ms) * TILE;
        run_step<false>(s1, nullptr, x + ((size_t)mbase * T_ + t) * D_,
                        hd, nullptr, c, biasr, uc,
                        smem, sb32, tid, lane, wm, wn, rank,
                        a_rowoff, a_half, b_rowoff, b_half);
    }

    // ---- phase B: layer 1 (K=512; x chunks prefetched, h chunks per step) ----
    if (tid == 0) {
        bulk_in(sb32 + SW_OFF, (char*)g_W1 + (size_t)rank * 131072, 131072, mbW);
#pragma unroll
        for (int p = 0; p < 4; p++)
            bulk_in(sb32 + RING_OFF + p * CH,
                    (const char*)g_h1seq + (size_t)ms * TILE + p * CH, CH,
                    sb32 + SMBAR_OFF + p * 8);
    }
#pragma unroll
    for (int nj = 0; nj < 4; nj++) {
        biasr[nj * 2 + 0] = g_b1[nbase + wn * 32 + nj * 8 + q * 2 + 0];
        biasr[nj * 2 + 1] = g_b1[nbase + wn * 32 + nj * 8 + q * 2 + 1];
    }
#pragma unroll
    for (int i = 0; i < 8; i++) c[i] = 0.f;
    mbar_wait(mbW, 1);

#pragma unroll 1
    for (int t = 0; t < T_; t++) {
        const char* s1 = (t == 0) ? zt
                       : (const char*)(((t - 1) & 1) ? g_h2b : g_h2a) + (size_t)ms * TILE;
        const char* nx = (t + 1 < T_)
                       ? ((const char*)g_h1seq + ((size_t)(t + 1) * 16 + ms) * TILE)
                       : (const char*)nullptr;
        bool fin = (t == T_ - 1);
        char* hd = (char*)((t & 1) ? g_h2b : g_h2a) + (size_t)ms * TILE;
        float* fd = fin ? (g_h2f + (size_t)mbase * H_ + rank * 32) : (float*)nullptr;
        run_step<true>(s1, nx, nullptr, hd, fd, c, biasr, uc,
                       smem, sb32, tid, lane, wm, wn, rank,
                       a_rowoff, a_half, b_rowoff, b_half);
    }
}

// ---------------- final FC ----------------
__global__ void k_fc(const float* __restrict__ Wfc, const float* __restrict__ bfc,
                     float* __restrict__ out) {
    int b = blockIdx.x;
    int o = threadIdx.y;
    int lane = threadIdx.x;
    const float* hr = g_h2f + (size_t)b * H_;
    const float* wr = Wfc + (size_t)o * H_;
    float s = 0.f;
    for (int j = lane; j < H_; j += 32) s += hr[j] * wr[j];
#pragma unroll
    for (int off = 16; off; off >>= 1) s += __shfl_xor_sync(0xffffffffu, s, off);
    if (lane == 0) out[b * 6 + o] = s + bfc[o];
}

// ---------------- host ----------------
extern "C" void kernel_launch(void* const* d_in, const int* in_sizes, int n_in,
                              void* d_out, int out_size) {
    const float* x     = (const float*)d_in[0];
    const float* W_ih0 = (const float*)d_in[1];
    const float* W_hh0 = (const float*)d_in[2];
    const float* b_ih0 = (const float*)d_in[3];
    const float* b_hh0 = (const float*)d_in[4];
    const float* W_ih1 = (const float*)d_in[5];
    const float* W_hh1 = (const float*)d_in[6];
    const float* b_ih1 = (const float*)d_in[7];
    const float* b_hh1 = (const float*)d_in[8];
    const float* W_fc  = (const float*)d_in[9];
    const float* b_fc  = (const float*)d_in[10];

    cudaFuncSetAttribute(k_lstm, cudaFuncAttributeMaxDynamicSharedMemorySize, SMEM_TOTAL);

    k_init<<<256, 256>>>();
    k_pack0<<<512, 256>>>(W_ih0, W_hh0, b_ih0, b_hh0);
    k_pack1<<<1024, 256>>>(W_ih1, W_hh1, b_ih1, b_hh1);

    k_lstm<<<dim3(CL, 16), THREADS, SMEM_TOTAL>>>(x);

    k_fc<<<B_, dim3(32, 6)>>>(W_fc, b_fc, (float*)d_out);
}